// round 3
// baseline (speedup 1.0000x reference)
#include <cuda_runtime.h>
#include <math.h>
#include <stdint.h>

// Problem constants
#define B_    8
#define S_    512
#define H_    4096
#define HQ_   32
#define HKV_  8
#define D_    128
#define L_    1536
#define T_    2048          // L_ + S_
#define NT_   (B_*S_)       // 4096 tokens
#define THETA_ 500000.0f

// ---------------- scratch (device globals; no runtime allocation) ----------
__device__ float g_q   [(size_t)NT_*HQ_ *D_];   // 4096 x 4096
__device__ float g_ktmp[(size_t)NT_*HKV_*D_];   // 4096 x 1024
__device__ float g_vtmp[(size_t)NT_*HKV_*D_];   // 4096 x 1024
__device__ float g_K   [(size_t)B_*T_*HKV_*D_]; // 8 x 2048 x 8 x 128
__device__ float g_V   [(size_t)B_*T_*HKV_*D_];
__device__ float g_att [(size_t)NT_*HQ_ *D_];   // 4096 x 4096

// ============================================================================
// GEMM via mma.sync tf32 (portable PTX; lowers to tensor-pipe HMMA on sm_103)
// C[M,N] = A[M,K] @ B[K,N], row-major fp32. 2-term tf32 split, 3 MMAs/product.
// BM=BN=128, BK=32, 256 threads (8 warps, 2x4 grid, 64x32 per warp).
// ============================================================================
#define AS_STRIDE 68            // 32 k * 2 (hi,lo) + 4 pad floats
#define BS_STRIDE 260           // 128 n * 2 (hi,lo) + 4 pad floats
#define GEMM_SMEM ((128*AS_STRIDE + 32*BS_STRIDE) * 4)   // 68096 bytes

__device__ __forceinline__ uint32_t f2tf32(float x) {
    uint32_t r;
    asm("cvt.rna.tf32.f32 %0, %1;" : "=r"(r) : "f"(x));
    return r;
}

#define MMA_TF32(c, A0, A1, A2, A3, Bb0, Bb1)                                    \
    asm volatile("mma.sync.aligned.m16n8k8.row.col.f32.tf32.tf32.f32 "           \
                 "{%0,%1,%2,%3}, {%4,%5,%6,%7}, {%8,%9}, {%0,%1,%2,%3};"         \
                 : "+f"((c)[0]), "+f"((c)[1]), "+f"((c)[2]), "+f"((c)[3])        \
                 : "r"(A0), "r"(A1), "r"(A2), "r"(A3), "r"(Bb0), "r"(Bb1))

__global__ __launch_bounds__(256) void gemm_tf32mma(
    const float* __restrict__ A, const float* __restrict__ Bm,
    float* __restrict__ C, int M, int N, int K)
{
    extern __shared__ float sm[];
    float* As = sm;                       // [128][AS_STRIDE]
    float* Bs = sm + 128 * AS_STRIDE;     // [32][BS_STRIDE]

    const int tid  = threadIdx.x;
    const int lane = tid & 31;
    const int wid  = tid >> 5;
    const int gid  = lane >> 2;           // 0..7
    const int tig  = lane & 3;            // 0..3
    const int wm   = (wid >> 2) * 64;     // warp row base (0 or 64)
    const int wn   = (wid & 3) * 32;      // warp col base (0,32,64,96)
    const int bm   = blockIdx.y * 128;
    const int bn   = blockIdx.x * 128;

    const int aRow = tid >> 1;            // 0..127
    const int aCol = (tid & 1) * 16;      // 0 or 16
    const int bRow = tid >> 3;            // 0..31
    const int bCol = (tid & 7) * 16;      // 0..112

    const float* Ag = A + (size_t)(bm + aRow) * K + aCol;
    const float* Bg = Bm + (size_t)bRow * N + bn + bCol;

    float acc[16][4];
#pragma unroll
    for (int i = 0; i < 16; i++) {
        acc[i][0] = 0.f; acc[i][1] = 0.f; acc[i][2] = 0.f; acc[i][3] = 0.f;
    }

    float ab[16], bb[16];

    // ---- prologue: load K-chunk 0 into registers ----
#pragma unroll
    for (int v = 0; v < 4; v++) {
        float4 t = *reinterpret_cast<const float4*>(Ag + v * 4);
        ab[v*4+0] = t.x; ab[v*4+1] = t.y; ab[v*4+2] = t.z; ab[v*4+3] = t.w;
        float4 u = *reinterpret_cast<const float4*>(Bg + v * 4);
        bb[v*4+0] = u.x; bb[v*4+1] = u.y; bb[v*4+2] = u.z; bb[v*4+3] = u.w;
    }
    // convert + store to smem (hi/lo interleaved)
#pragma unroll
    for (int e = 0; e < 16; e += 2) {
        uint32_t h0 = f2tf32(ab[e]);
        uint32_t l0 = f2tf32(ab[e]   - __uint_as_float(h0));
        uint32_t h1 = f2tf32(ab[e+1]);
        uint32_t l1 = f2tf32(ab[e+1] - __uint_as_float(h1));
        *reinterpret_cast<uint4*>(&As[aRow * AS_STRIDE + (aCol + e) * 2]) =
            make_uint4(h0, l0, h1, l1);
        uint32_t g0 = f2tf32(bb[e]);
        uint32_t m0 = f2tf32(bb[e]   - __uint_as_float(g0));
        uint32_t g1 = f2tf32(bb[e+1]);
        uint32_t m1 = f2tf32(bb[e+1] - __uint_as_float(g1));
        *reinterpret_cast<uint4*>(&Bs[bRow * BS_STRIDE + (bCol + e) * 2]) =
            make_uint4(g0, m0, g1, m1);
    }
    __syncthreads();

    const int nk = K / 32;
    for (int ck = 0; ck < nk; ck++) {
        const bool has_next = (ck + 1) < nk;
        // prefetch next chunk into registers (overlaps with MMA below)
        if (has_next) {
            const float* Agn = Ag + (ck + 1) * 32;
            const float* Bgn = Bg + (size_t)(ck + 1) * 32 * N;
#pragma unroll
            for (int v = 0; v < 4; v++) {
                float4 t = *reinterpret_cast<const float4*>(Agn + v * 4);
                ab[v*4+0] = t.x; ab[v*4+1] = t.y; ab[v*4+2] = t.z; ab[v*4+3] = t.w;
                float4 u = *reinterpret_cast<const float4*>(Bgn + v * 4);
                bb[v*4+0] = u.x; bb[v*4+1] = u.y; bb[v*4+2] = u.z; bb[v*4+3] = u.w;
            }
        }

        // ---- compute: 4 k-steps of m16n8k8 over the 64x32 warp tile ----
#pragma unroll
        for (int k0 = 0; k0 < 4; k0++) {
            const int kb = k0 * 8;
            uint2 bf[4][2];
#pragma unroll
            for (int j = 0; j < 4; j++) {
                const int n = wn + j * 8 + gid;
                bf[j][0] = *reinterpret_cast<const uint2*>(
                    &Bs[(kb + tig) * BS_STRIDE + n * 2]);
                bf[j][1] = *reinterpret_cast<const uint2*>(
                    &Bs[(kb + tig + 4) * BS_STRIDE + n * 2]);
            }
#pragma unroll
            for (int i = 0; i < 4; i++) {
                const int m = wm + i * 16 + gid;
                uint2 a0 = *reinterpret_cast<const uint2*>(
                    &As[m * AS_STRIDE + (kb + tig) * 2]);
                uint2 a1 = *reinterpret_cast<const uint2*>(
                    &As[(m + 8) * AS_STRIDE + (kb + tig) * 2]);
                uint2 a2 = *reinterpret_cast<const uint2*>(
                    &As[m * AS_STRIDE + (kb + tig + 4) * 2]);
                uint2 a3 = *reinterpret_cast<const uint2*>(
                    &As[(m + 8) * AS_STRIDE + (kb + tig + 4) * 2]);
#pragma unroll
                for (int j = 0; j < 4; j++) {
                    float* c = acc[i * 4 + j];
                    MMA_TF32(c, a0.x, a1.x, a2.x, a3.x, bf[j][0].x, bf[j][1].x);
                    MMA_TF32(c, a0.x, a1.x, a2.x, a3.x, bf[j][0].y, bf[j][1].y);
                    MMA_TF32(c, a0.y, a1.y, a2.y, a3.y, bf[j][0].x, bf[j][1].x);
                }
            }
        }
        __syncthreads();

        if (has_next) {
#pragma unroll
            for (int e = 0; e < 16; e += 2) {
                uint32_t h0 = f2tf32(ab[e]);
                uint32_t l0 = f2tf32(ab[e]   - __uint_as_float(h0));
                uint32_t h1 = f2tf32(ab[e+1]);
                uint32_t l1 = f2tf32(ab[e+1] - __uint_as_float(h1));
                *reinterpret_cast<uint4*>(&As[aRow * AS_STRIDE + (aCol + e) * 2]) =
                    make_uint4(h0, l0, h1, l1);
                uint32_t g0 = f2tf32(bb[e]);
                uint32_t m0 = f2tf32(bb[e]   - __uint_as_float(g0));
                uint32_t g1 = f2tf32(bb[e+1]);
                uint32_t m1 = f2tf32(bb[e+1] - __uint_as_float(g1));
                *reinterpret_cast<uint4*>(&Bs[bRow * BS_STRIDE + (bCol + e) * 2]) =
                    make_uint4(g0, m0, g1, m1);
            }
            __syncthreads();
        }
    }

    // ---- epilogue: direct float2 stores ----
#pragma unroll
    for (int i = 0; i < 4; i++) {
        const int row = bm + wm + i * 16 + gid;
#pragma unroll
        for (int j = 0; j < 4; j++) {
            const int col = bn + wn + j * 8 + tig * 2;
            const float* c = acc[i * 4 + j];
            *reinterpret_cast<float2*>(&C[(size_t)row * N + col]) =
                make_float2(c[0], c[1]);
            *reinterpret_cast<float2*>(&C[(size_t)(row + 8) * N + col]) =
                make_float2(c[2], c[3]);
        }
    }
}

// ---------------- RoPE on Q (in place) -------------------------------------
__global__ void rope_q_kernel()
{
    int idx = blockIdx.x * blockDim.x + threadIdx.x;
    if (idx >= NT_ * HQ_ * 64) return;
    int d   = idx & 63;
    int th  = idx >> 6;
    int tok = th >> 5;
    int s   = tok & (S_ - 1);
    float pos = (float)(L_ + s);
    float inv = powf(THETA_, -(float)d * (1.0f / 64.0f));
    float ang = pos * inv;
    float c = cosf(ang), sn = sinf(ang);
    float* base = g_q + (size_t)th * D_;
    float x1 = base[d], x2 = base[d + 64];
    base[d]      = x1 * c - x2 * sn;
    base[d + 64] = x2 * c + x1 * sn;
}

// ---------------- RoPE on new K + scatter into combined K buffer -----------
__global__ void rope_scatter_k_kernel()
{
    int idx = blockIdx.x * blockDim.x + threadIdx.x;
    if (idx >= NT_ * HKV_ * 64) return;
    int d   = idx & 63;
    int th  = idx >> 6;
    int tok = th >> 3;
    int kvh = th & 7;
    int b   = tok >> 9;
    int s   = tok & 511;
    float pos = (float)(L_ + s);
    float inv = powf(THETA_, -(float)d * (1.0f / 64.0f));
    float ang = pos * inv;
    float c = cosf(ang), sn = sinf(ang);
    const float* src = g_ktmp + (size_t)th * D_;
    float* dst = g_K + (((size_t)(b * T_ + L_ + s)) * HKV_ + kvh) * D_;
    float x1 = src[d], x2 = src[d + 64];
    dst[d]      = x1 * c - x2 * sn;
    dst[d + 64] = x2 * c + x1 * sn;
}

// ---------------- scatter new V into combined V buffer (float4) ------------
__global__ void scatter_v_kernel()
{
    int idx = blockIdx.x * blockDim.x + threadIdx.x;
    const int n = NT_ * HKV_ * D_ / 4;
    if (idx >= n) return;
    const int per = HKV_ * D_ / 4;   // 256
    int tok = idx / per;
    int r   = idx - tok * per;
    int b   = tok >> 9;
    int s   = tok & 511;
    const float4* src = reinterpret_cast<const float4*>(g_vtmp);
    float4* dst = reinterpret_cast<float4*>(g_V);
    dst[((size_t)(b * T_ + L_ + s)) * per + r] = src[idx];
}

// ---------------- copy K/V cache into combined buffers (float4) ------------
__global__ void copy_cache_kernel(const float4* __restrict__ kc,
                                  const float4* __restrict__ vc)
{
    int idx = blockIdx.x * blockDim.x + threadIdx.x;
    const int n = B_ * L_ * HKV_ * D_ / 4;
    if (idx >= n) return;
    const int perb_src = L_ * HKV_ * D_ / 4;
    const int perb_dst = T_ * HKV_ * D_ / 4;
    int b = idx / perb_src;
    int r = idx - b * perb_src;
    float4* dk = reinterpret_cast<float4*>(g_K);
    float4* dv = reinterpret_cast<float4*>(g_V);
    dk[(size_t)b * perb_dst + r] = kc[idx];
    dv[(size_t)b * perb_dst + r] = vc[idx];
}

// ---------------- flash attention, fp32, 64q x 64k tiles -------------------
#define ATT_SMEM_FLOATS (3 * 64 * 129 + 64 * 65 + 3 * 64)
#define ATT_SMEM_BYTES  (ATT_SMEM_FLOATS * 4)

__global__ __launch_bounds__(256) void attn_kernel()
{
    extern __shared__ float sm[];
    float* Qs   = sm;
    float* Ks   = sm + 64 * 129;
    float* Vs   = sm + 2 * 64 * 129;
    float* Ss   = sm + 3 * 64 * 129;
    float* m_sh = Ss + 64 * 65;
    float* l_sh = m_sh + 64;
    float* f_sh = l_sh + 64;

    const int tid = threadIdx.x;
    const int qt  = blockIdx.x;
    const int hq  = blockIdx.y;
    const int b   = blockIdx.z;
    const int kvh = hq >> 2;
    const int s0  = qt * 64;

    const int lr = tid >> 2;
    const int lc = (tid & 3) * 32;

    {
        const float* src = g_q + ((size_t)(b * S_ + s0 + lr)) * (HQ_ * D_) + hq * D_ + lc;
        float* dq = Qs + lr * 129 + lc;
#pragma unroll
        for (int i = 0; i < 32; i += 4) {
            float4 v = *reinterpret_cast<const float4*>(src + i);
            dq[i] = v.x; dq[i + 1] = v.y; dq[i + 2] = v.z; dq[i + 3] = v.w;
        }
    }
    if (tid < 64) { m_sh[tid] = -1e30f; l_sh[tid] = 0.0f; }

    const int ty = tid >> 4;
    const int tx = tid & 15;

    float acc[4][8];
#pragma unroll
    for (int i = 0; i < 4; i++)
#pragma unroll
        for (int j = 0; j < 8; j++) acc[i][j] = 0.0f;

    const int ntiles = 25 + qt;

    for (int kt = 0; kt < ntiles; kt++) {
        __syncthreads();
        {
            const float* src = g_K + (((size_t)(b * T_ + kt * 64 + lr)) * HKV_ + kvh) * D_ + lc;
            float* dk = Ks + lr * 129 + lc;
#pragma unroll
            for (int i = 0; i < 32; i += 4) {
                float4 v = *reinterpret_cast<const float4*>(src + i);
                dk[i] = v.x; dk[i + 1] = v.y; dk[i + 2] = v.z; dk[i + 3] = v.w;
            }
        }
        __syncthreads();

        float aS[4][4];
#pragma unroll
        for (int i = 0; i < 4; i++)
#pragma unroll
            for (int j = 0; j < 4; j++) aS[i][j] = 0.0f;

        const float* qb = Qs + (ty * 4) * 129;
        const float* kb = Ks + (tx * 4) * 129;
#pragma unroll 4
        for (int d = 0; d < 128; d++) {
            float ra[4], rb[4];
#pragma unroll
            for (int i = 0; i < 4; i++) ra[i] = qb[i * 129 + d];
#pragma unroll
            for (int j = 0; j < 4; j++) rb[j] = kb[j * 129 + d];
#pragma unroll
            for (int i = 0; i < 4; i++)
#pragma unroll
                for (int j = 0; j < 4; j++)
                    aS[i][j] += ra[i] * rb[j];
        }

        const bool diag = (kt == ntiles - 1);
        const float scl = 0.08838834764831845f;
#pragma unroll
        for (int i = 0; i < 4; i++) {
            int row = ty * 4 + i;
#pragma unroll
            for (int j = 0; j < 4; j++) {
                int col = tx * 4 + j;
                float v = aS[i][j] * scl;
                if (diag && col > row) v = -1e30f;
                Ss[row * 65 + col] = v;
            }
        }
        __syncthreads();

        if (tid < 64) {
            float mold = m_sh[tid];
            float mx = mold;
            float* sr = Ss + tid * 65;
            for (int j = 0; j < 64; j++) mx = fmaxf(mx, sr[j]);
            float sum = 0.0f;
            for (int j = 0; j < 64; j++) {
                float p = expf(sr[j] - mx);
                sr[j] = p;
                sum += p;
            }
            float f = expf(mold - mx);
            l_sh[tid] = l_sh[tid] * f + sum;
            m_sh[tid] = mx;
            f_sh[tid] = f;
        }
        __syncthreads();

#pragma unroll
        for (int i = 0; i < 4; i++) {
            float f = f_sh[ty * 4 + i];
#pragma unroll
            for (int n = 0; n < 8; n++) acc[i][n] *= f;
        }
        {
            const float* src = g_V + (((size_t)(b * T_ + kt * 64 + lr)) * HKV_ + kvh) * D_ + lc;
            float* dv = Vs + lr * 129 + lc;
#pragma unroll
            for (int i = 0; i < 32; i += 4) {
                float4 v = *reinterpret_cast<const float4*>(src + i);
                dv[i] = v.x; dv[i + 1] = v.y; dv[i + 2] = v.z; dv[i + 3] = v.w;
            }
        }
        __syncthreads();

        const float* pb = Ss + (ty * 4) * 65;
        const float* vb = Vs + tx * 8;
#pragma unroll 2
        for (int j = 0; j < 64; j++) {
            float p0 = pb[j];
            float p1 = pb[65 + j];
            float p2 = pb[130 + j];
            float p3 = pb[195 + j];
            const float* vr = vb + j * 129;
#pragma unroll
            for (int n = 0; n < 8; n++) {
                float v = vr[n];
                acc[0][n] += p0 * v;
                acc[1][n] += p1 * v;
                acc[2][n] += p2 * v;
                acc[3][n] += p3 * v;
            }
        }
    }

    __syncthreads();
    float li[4];
#pragma unroll
    for (int i = 0; i < 4; i++) li[i] = 1.0f / l_sh[ty * 4 + i];

    float* dst = g_att + ((size_t)(b * S_ + s0 + ty * 4)) * (HQ_ * D_) + hq * D_ + tx * 8;
#pragma unroll
    for (int i = 0; i < 4; i++) {
        float4 v0 = make_float4(acc[i][0] * li[i], acc[i][1] * li[i],
                                acc[i][2] * li[i], acc[i][3] * li[i]);
        float4 v1 = make_float4(acc[i][4] * li[i], acc[i][5] * li[i],
                                acc[i][6] * li[i], acc[i][7] * li[i]);
        *reinterpret_cast<float4*>(dst + (size_t)i * (HQ_ * D_))     = v0;
        *reinterpret_cast<float4*>(dst + (size_t)i * (HQ_ * D_) + 4) = v1;
    }
}

// ---------------- launcher --------------------------------------------------
extern "C" void kernel_launch(void* const* d_in, const int* in_sizes, int n_in,
                              void* d_out, int out_size)
{
    const float* hidden  = (const float*)d_in[0];
    const float* k_cache = (const float*)d_in[1];
    const float* v_cache = (const float*)d_in[2];
    const float* wq      = (const float*)d_in[3];
    const float* wk      = (const float*)d_in[4];
    const float* wv      = (const float*)d_in[5];
    const float* wo      = (const float*)d_in[6];
    float* out = (float*)d_out;

    float *q, *ktmp, *vtmp, *att;
    cudaGetSymbolAddress((void**)&q,    g_q);
    cudaGetSymbolAddress((void**)&ktmp, g_ktmp);
    cudaGetSymbolAddress((void**)&vtmp, g_vtmp);
    cudaGetSymbolAddress((void**)&att,  g_att);

    cudaFuncSetAttribute(gemm_tf32mma,
                         cudaFuncAttributeMaxDynamicSharedMemorySize, GEMM_SMEM);
    cudaFuncSetAttribute(attn_kernel,
                         cudaFuncAttributeMaxDynamicSharedMemorySize, ATT_SMEM_BYTES);

    // projections (tensor-pipe tf32 split GEMM)
    gemm_tf32mma<<<dim3(H_ / 128, NT_ / 128), 256, GEMM_SMEM>>>(hidden, wq, q,    NT_, H_,         H_);
    gemm_tf32mma<<<dim3((HKV_ * D_) / 128, NT_ / 128), 256, GEMM_SMEM>>>(hidden, wk, ktmp, NT_, HKV_ * D_, H_);
    gemm_tf32mma<<<dim3((HKV_ * D_) / 128, NT_ / 128), 256, GEMM_SMEM>>>(hidden, wv, vtmp, NT_, HKV_ * D_, H_);

    // rope + KV assembly
    rope_q_kernel<<<(NT_ * HQ_ * 64) / 256, 256>>>();
    rope_scatter_k_kernel<<<(NT_ * HKV_ * 64) / 256, 256>>>();
    scatter_v_kernel<<<(NT_ * HKV_ * D_ / 4) / 256, 256>>>();
    copy_cache_kernel<<<(B_ * L_ * HKV_ * D_ / 4) / 256, 256>>>(
        (const float4*)k_cache, (const float4*)v_cache);

    // attention (fp32 flash)
    attn_kernel<<<dim3(S_ / 64, HQ_, B_), 256, ATT_SMEM_BYTES>>>();

    // output projection
    gemm_tf32mma<<<dim3(H_ / 128, NT_ / 128), 256, GEMM_SMEM>>>(att, wo, out, NT_, H_, H_);
}

// round 4
// speedup vs baseline: 1.7786x; 1.7786x over previous
#include <cuda_runtime.h>
#include <cuda_bf16.h>
#include <math.h>
#include <stdint.h>

// Problem constants
#define B_    8
#define S_    512
#define H_    4096
#define HQ_   32
#define HKV_  8
#define D_    128
#define L_    1536
#define T_    2048          // L_ + S_
#define NT_   (B_*S_)       // 4096 tokens
#define THETA_ 500000.0f

// ---------------- scratch (device globals; no runtime allocation) ----------
__device__ float g_q   [(size_t)NT_*HQ_ *D_];   // 4096 x 4096
__device__ float g_ktmp[(size_t)NT_*HKV_*D_];
__device__ float g_vtmp[(size_t)NT_*HKV_*D_];
__device__ float g_K   [(size_t)B_*T_*HKV_*D_];
__device__ float g_V   [(size_t)B_*T_*HKV_*D_];
__device__ float g_att [(size_t)NT_*HQ_ *D_];   // 4096 x 4096

// bf16 split buffers (hi/lo). Weights are stored TRANSPOSED: [N][K].
__device__ __nv_bfloat16 g_hid_h [(size_t)NT_*H_];
__device__ __nv_bfloat16 g_hid_l [(size_t)NT_*H_];
__device__ __nv_bfloat16 g_wqT_h [(size_t)H_*H_];
__device__ __nv_bfloat16 g_wqT_l [(size_t)H_*H_];
__device__ __nv_bfloat16 g_wkT_h [(size_t)H_*HKV_*D_];
__device__ __nv_bfloat16 g_wkT_l [(size_t)H_*HKV_*D_];
__device__ __nv_bfloat16 g_wvT_h [(size_t)H_*HKV_*D_];
__device__ __nv_bfloat16 g_wvT_l [(size_t)H_*HKV_*D_];
__device__ __nv_bfloat16 g_woT_h [(size_t)H_*H_];
__device__ __nv_bfloat16 g_woT_l [(size_t)H_*H_];
__device__ __nv_bfloat16 g_attb_h[(size_t)NT_*H_];
__device__ __nv_bfloat16 g_attb_l[(size_t)NT_*H_];

// ---------------- helpers ---------------------------------------------------
__device__ __forceinline__ uint32_t smem_u32(const void* p) {
    uint32_t r;
    asm("{ .reg .u64 t; cvta.to.shared.u64 t, %1; cvt.u32.u64 %0, t; }"
        : "=r"(r) : "l"(p));
    return r;
}

__device__ __forceinline__ uint16_t bf_hi(float x) {
    __nv_bfloat16 b = __float2bfloat16(x);
    return *reinterpret_cast<uint16_t*>(&b);
}
__device__ __forceinline__ float bf_back(uint16_t u) {
    __nv_bfloat16 b = *reinterpret_cast<__nv_bfloat16*>(&u);
    return __bfloat162float(b);
}

#define CP_ASYNC16(dst, src) \
    asm volatile("cp.async.cg.shared.global [%0], [%1], 16;" :: "r"(dst), "l"(src))
#define CP_COMMIT() asm volatile("cp.async.commit_group;")
#define CP_WAIT1()  asm volatile("cp.async.wait_group 1;")
#define CP_WAIT0()  asm volatile("cp.async.wait_group 0;")

#define LDSM4(r, a) \
    asm volatile("ldmatrix.sync.aligned.m8n8.x4.shared.b16 {%0,%1,%2,%3}, [%4];" \
                 : "=r"((r)[0]), "=r"((r)[1]), "=r"((r)[2]), "=r"((r)[3]) : "r"(a))
#define LDSM2(r, a) \
    asm volatile("ldmatrix.sync.aligned.m8n8.x2.shared.b16 {%0,%1}, [%2];" \
                 : "=r"((r)[0]), "=r"((r)[1]) : "r"(a))

#define MMA_BF16(c, a, b) \
    asm volatile("mma.sync.aligned.m16n8k16.row.col.f32.bf16.bf16.f32 " \
                 "{%0,%1,%2,%3}, {%4,%5,%6,%7}, {%8,%9}, {%0,%1,%2,%3};" \
                 : "+f"((c)[0]), "+f"((c)[1]), "+f"((c)[2]), "+f"((c)[3]) \
                 : "r"((a)[0]), "r"((a)[1]), "r"((a)[2]), "r"((a)[3]), \
                   "r"((b)[0]), "r"((b)[1]))

// ---------------- fp32 -> bf16 hi/lo split (same layout) --------------------
__global__ void conv_split(const float4* __restrict__ in,
                           uint2* __restrict__ oh, uint2* __restrict__ ol, int n4)
{
    int i = blockIdx.x * blockDim.x + threadIdx.x;
    if (i >= n4) return;
    float4 v = in[i];
    uint16_t hx = bf_hi(v.x), hy = bf_hi(v.y), hz = bf_hi(v.z), hw = bf_hi(v.w);
    uint16_t lx = bf_hi(v.x - bf_back(hx));
    uint16_t ly = bf_hi(v.y - bf_back(hy));
    uint16_t lz = bf_hi(v.z - bf_back(hz));
    uint16_t lw = bf_hi(v.w - bf_back(hw));
    oh[i] = make_uint2((uint32_t)hx | ((uint32_t)hy << 16),
                       (uint32_t)hz | ((uint32_t)hw << 16));
    ol[i] = make_uint2((uint32_t)lx | ((uint32_t)ly << 16),
                       (uint32_t)lz | ((uint32_t)lw << 16));
}

// ---------------- fp32 [K][N] -> bf16 hi/lo transposed [N][K] ---------------
__global__ void conv_splitT(const float* __restrict__ in,
                            __nv_bfloat16* __restrict__ oh,
                            __nv_bfloat16* __restrict__ ol, int K, int N)
{
    __shared__ float t[32][33];
    const int n0 = blockIdx.x * 32;
    const int k0 = blockIdx.y * 32;
    const int x = threadIdx.x, y = threadIdx.y;   // 32 x 8
#pragma unroll
    for (int dy = 0; dy < 4; dy++)
        t[y + dy * 8][x] = in[(size_t)(k0 + y + dy * 8) * N + n0 + x];
    __syncthreads();
#pragma unroll
    for (int dy = 0; dy < 4; dy++) {
        int nrow = y + dy * 8;
        float v = t[x][nrow];
        uint16_t h = bf_hi(v);
        uint16_t l = bf_hi(v - bf_back(h));
        size_t o = (size_t)(n0 + nrow) * K + k0 + x;
        oh[o] = *reinterpret_cast<__nv_bfloat16*>(&h);
        ol[o] = *reinterpret_cast<__nv_bfloat16*>(&l);
    }
}

// ============================================================================
// bf16-split GEMM. C[M,N] = A[M,K] @ B[N,K]^T (B pre-transposed).
// BM=BN=128, BK=32, 256 threads, 8 warps (2x4), warp tile 64x32.
// smem: 2 stages x { Ah 8K | Al 8K | Bh 8K | Bl 8K } = 64KB, cp.async pipelined.
// 3 MMAs per product: Ahi*Bhi + Ahi*Blo + Alo*Bhi.
// ============================================================================
#define GEMM_SMEM (2 * 32768)

__global__ __launch_bounds__(256) void gemm_bf16(
    const __nv_bfloat16* __restrict__ Ah, const __nv_bfloat16* __restrict__ Al,
    const __nv_bfloat16* __restrict__ Bh, const __nv_bfloat16* __restrict__ Bl,
    float* __restrict__ C, int M, int N, int K)
{
    extern __shared__ char smem[];
    const uint32_t sb = smem_u32(smem);
    const int tid  = threadIdx.x;
    const int lane = tid & 31;
    const int wid  = tid >> 5;
    const int bm   = blockIdx.y * 128;
    const int bn   = blockIdx.x * 128;
    const int wm   = (wid >> 2) * 64;
    const int wn   = (wid & 3) * 32;

    // loader: granule = (row, 16B-chunk); swizzle chunk' = chunk ^ ((row>>1)&3)
    const int lrow = tid >> 2;        // 0..63
    const int lchk = tid & 3;
    const uint32_t dsw = (uint32_t)(lrow * 64 + ((lchk ^ ((lrow >> 1) & 3)) * 16));

    const __nv_bfloat16* srcA[2] = {Ah, Al};
    const __nv_bfloat16* srcB[2] = {Bh, Bl};

    // fragment lane addressing
    const int arow = ((lane >> 3) & 1) * 8 + (lane & 7);
    const int akc  = lane >> 4;                 // 0/1
    const int aph  = ((lane & 7) >> 1) & 3;
    const int brow = lane & 7;
    const int bkc  = (lane >> 3) & 1;
    const int bph  = (brow >> 1) & 3;

    const uint32_t aBase = (uint32_t)((wm + arow) * 64);
    const uint32_t bBase = (uint32_t)((wn + brow) * 64);

    float acc[4][4][4];
#pragma unroll
    for (int i = 0; i < 4; i++)
#pragma unroll
        for (int j = 0; j < 4; j++) {
            acc[i][j][0] = 0.f; acc[i][j][1] = 0.f;
            acc[i][j][2] = 0.f; acc[i][j][3] = 0.f;
        }

    const int nk = K / 32;

    // issue loads for chunk ck into stage st
    auto issue = [&](int st, int k0) {
        const uint32_t s = sb + st * 32768;
#pragma unroll
        for (int p = 0; p < 2; p++) {
            const __nv_bfloat16* g = srcA[p] + (size_t)(bm + lrow) * K + k0 + lchk * 8;
            uint32_t d = s + p * 8192 + dsw;
            CP_ASYNC16(d, g);
            CP_ASYNC16(d + 4096, g + (size_t)64 * K);
        }
#pragma unroll
        for (int p = 0; p < 2; p++) {
            const __nv_bfloat16* g = srcB[p] + (size_t)(bn + lrow) * K + k0 + lchk * 8;
            uint32_t d = s + 16384 + p * 8192 + dsw;
            CP_ASYNC16(d, g);
            CP_ASYNC16(d + 4096, g + (size_t)64 * K);
        }
        CP_COMMIT();
    };

    issue(0, 0);
    if (nk > 1) issue(1, 32);

    for (int ck = 0; ck < nk; ck++) {
        if (ck + 1 < nk) { CP_WAIT1(); } else { CP_WAIT0(); }
        __syncthreads();

        const uint32_t s  = sb + (ck & 1) * 32768;
        const uint32_t sAh = s + aBase;
        const uint32_t sAl = s + 8192 + aBase;
        const uint32_t sBh = s + 16384 + bBase;
        const uint32_t sBl = s + 24576 + bBase;

#pragma unroll
        for (int ks = 0; ks < 2; ks++) {
            const uint32_t cA = (uint32_t)(((ks * 2 + akc) ^ aph) * 16);
            const uint32_t cB = (uint32_t)(((ks * 2 + bkc) ^ bph) * 16);

            uint32_t aF[4][4];
#pragma unroll
            for (int i = 0; i < 4; i++) LDSM4(aF[i], sAh + i * 1024 + cA);
            uint32_t bH[4][2], bL[4][2];
#pragma unroll
            for (int j = 0; j < 4; j++) LDSM2(bH[j], sBh + j * 512 + cB);
#pragma unroll
            for (int j = 0; j < 4; j++) LDSM2(bL[j], sBl + j * 512 + cB);

#pragma unroll
            for (int i = 0; i < 4; i++)
#pragma unroll
                for (int j = 0; j < 4; j++) MMA_BF16(acc[i][j], aF[i], bH[j]);
#pragma unroll
            for (int i = 0; i < 4; i++)
#pragma unroll
                for (int j = 0; j < 4; j++) MMA_BF16(acc[i][j], aF[i], bL[j]);

#pragma unroll
            for (int i = 0; i < 4; i++) LDSM4(aF[i], sAl + i * 1024 + cA);
#pragma unroll
            for (int i = 0; i < 4; i++)
#pragma unroll
                for (int j = 0; j < 4; j++) MMA_BF16(acc[i][j], aF[i], bH[j]);
        }
        __syncthreads();
        if (ck + 2 < nk) issue(ck & 1, (ck + 2) * 32);
    }

    // epilogue
    const int g4 = lane >> 2, t4 = lane & 3;
#pragma unroll
    for (int i = 0; i < 4; i++) {
        const int row = bm + wm + i * 16 + g4;
#pragma unroll
        for (int j = 0; j < 4; j++) {
            const int col = bn + wn + j * 8 + t4 * 2;
            *reinterpret_cast<float2*>(&C[(size_t)row * N + col]) =
                make_float2(acc[i][j][0], acc[i][j][1]);
            *reinterpret_cast<float2*>(&C[(size_t)(row + 8) * N + col]) =
                make_float2(acc[i][j][2], acc[i][j][3]);
        }
    }
}

// ---------------- RoPE on Q (in place) -------------------------------------
__global__ void rope_q_kernel()
{
    int idx = blockIdx.x * blockDim.x + threadIdx.x;
    if (idx >= NT_ * HQ_ * 64) return;
    int d   = idx & 63;
    int th  = idx >> 6;
    int tok = th >> 5;
    int s   = tok & (S_ - 1);
    float pos = (float)(L_ + s);
    float inv = powf(THETA_, -(float)d * (1.0f / 64.0f));
    float ang = pos * inv;
    float c = cosf(ang), sn = sinf(ang);
    float* base = g_q + (size_t)th * D_;
    float x1 = base[d], x2 = base[d + 64];
    base[d]      = x1 * c - x2 * sn;
    base[d + 64] = x2 * c + x1 * sn;
}

__global__ void rope_scatter_k_kernel()
{
    int idx = blockIdx.x * blockDim.x + threadIdx.x;
    if (idx >= NT_ * HKV_ * 64) return;
    int d   = idx & 63;
    int th  = idx >> 6;
    int tok = th >> 3;
    int kvh = th & 7;
    int b   = tok >> 9;
    int s   = tok & 511;
    float pos = (float)(L_ + s);
    float inv = powf(THETA_, -(float)d * (1.0f / 64.0f));
    float ang = pos * inv;
    float c = cosf(ang), sn = sinf(ang);
    const float* src = g_ktmp + (size_t)th * D_;
    float* dst = g_K + (((size_t)(b * T_ + L_ + s)) * HKV_ + kvh) * D_;
    float x1 = src[d], x2 = src[d + 64];
    dst[d]      = x1 * c - x2 * sn;
    dst[d + 64] = x2 * c + x1 * sn;
}

__global__ void scatter_v_kernel()
{
    int idx = blockIdx.x * blockDim.x + threadIdx.x;
    const int n = NT_ * HKV_ * D_ / 4;
    if (idx >= n) return;
    const int per = HKV_ * D_ / 4;
    int tok = idx / per;
    int r   = idx - tok * per;
    int b   = tok >> 9;
    int s   = tok & 511;
    const float4* src = reinterpret_cast<const float4*>(g_vtmp);
    float4* dst = reinterpret_cast<float4*>(g_V);
    dst[((size_t)(b * T_ + L_ + s)) * per + r] = src[idx];
}

__global__ void copy_cache_kernel(const float4* __restrict__ kc,
                                  const float4* __restrict__ vc)
{
    int idx = blockIdx.x * blockDim.x + threadIdx.x;
    const int n = B_ * L_ * HKV_ * D_ / 4;
    if (idx >= n) return;
    const int perb_src = L_ * HKV_ * D_ / 4;
    const int perb_dst = T_ * HKV_ * D_ / 4;
    int b = idx / perb_src;
    int r = idx - b * perb_src;
    float4* dk = reinterpret_cast<float4*>(g_K);
    float4* dv = reinterpret_cast<float4*>(g_V);
    dk[(size_t)b * perb_dst + r] = kc[idx];
    dv[(size_t)b * perb_dst + r] = vc[idx];
}

// ---------------- flash attention, fp32, 64q x 64k tiles -------------------
#define ATT_SMEM_FLOATS (3 * 64 * 129 + 64 * 65 + 3 * 64)
#define ATT_SMEM_BYTES  (ATT_SMEM_FLOATS * 4)

__global__ __launch_bounds__(256) void attn_kernel()
{
    extern __shared__ float sm[];
    float* Qs   = sm;
    float* Ks   = sm + 64 * 129;
    float* Vs   = sm + 2 * 64 * 129;
    float* Ss   = sm + 3 * 64 * 129;
    float* m_sh = Ss + 64 * 65;
    float* l_sh = m_sh + 64;
    float* f_sh = l_sh + 64;

    const int tid = threadIdx.x;
    const int qt  = blockIdx.x;
    const int hq  = blockIdx.y;
    const int b   = blockIdx.z;
    const int kvh = hq >> 2;
    const int s0  = qt * 64;

    const int lr = tid >> 2;
    const int lc = (tid & 3) * 32;

    {
        const float* src = g_q + ((size_t)(b * S_ + s0 + lr)) * (HQ_ * D_) + hq * D_ + lc;
        float* dq = Qs + lr * 129 + lc;
#pragma unroll
        for (int i = 0; i < 32; i += 4) {
            float4 v = *reinterpret_cast<const float4*>(src + i);
            dq[i] = v.x; dq[i + 1] = v.y; dq[i + 2] = v.z; dq[i + 3] = v.w;
        }
    }
    if (tid < 64) { m_sh[tid] = -1e30f; l_sh[tid] = 0.0f; }

    const int ty = tid >> 4;
    const int tx = tid & 15;

    float acc[4][8];
#pragma unroll
    for (int i = 0; i < 4; i++)
#pragma unroll
        for (int j = 0; j < 8; j++) acc[i][j] = 0.0f;

    const int ntiles = 25 + qt;

    for (int kt = 0; kt < ntiles; kt++) {
        __syncthreads();
        {
            const float* src = g_K + (((size_t)(b * T_ + kt * 64 + lr)) * HKV_ + kvh) * D_ + lc;
            float* dk = Ks + lr * 129 + lc;
#pragma unroll
            for (int i = 0; i < 32; i += 4) {
                float4 v = *reinterpret_cast<const float4*>(src + i);
                dk[i] = v.x; dk[i + 1] = v.y; dk[i + 2] = v.z; dk[i + 3] = v.w;
            }
        }
        __syncthreads();

        float aS[4][4];
#pragma unroll
        for (int i = 0; i < 4; i++)
#pragma unroll
            for (int j = 0; j < 4; j++) aS[i][j] = 0.0f;

        const float* qb = Qs + (ty * 4) * 129;
        const float* kb = Ks + (tx * 4) * 129;
#pragma unroll 4
        for (int d = 0; d < 128; d++) {
            float ra[4], rb[4];
#pragma unroll
            for (int i = 0; i < 4; i++) ra[i] = qb[i * 129 + d];
#pragma unroll
            for (int j = 0; j < 4; j++) rb[j] = kb[j * 129 + d];
#pragma unroll
            for (int i = 0; i < 4; i++)
#pragma unroll
                for (int j = 0; j < 4; j++)
                    aS[i][j] += ra[i] * rb[j];
        }

        const bool diag = (kt == ntiles - 1);
        const float scl = 0.08838834764831845f;
#pragma unroll
        for (int i = 0; i < 4; i++) {
            int row = ty * 4 + i;
#pragma unroll
            for (int j = 0; j < 4; j++) {
                int col = tx * 4 + j;
                float v = aS[i][j] * scl;
                if (diag && col > row) v = -1e30f;
                Ss[row * 65 + col] = v;
            }
        }
        __syncthreads();

        if (tid < 64) {
            float mold = m_sh[tid];
            float mx = mold;
            float* sr = Ss + tid * 65;
            for (int j = 0; j < 64; j++) mx = fmaxf(mx, sr[j]);
            float sum = 0.0f;
            for (int j = 0; j < 64; j++) {
                float p = expf(sr[j] - mx);
                sr[j] = p;
                sum += p;
            }
            float f = expf(mold - mx);
            l_sh[tid] = l_sh[tid] * f + sum;
            m_sh[tid] = mx;
            f_sh[tid] = f;
        }
        __syncthreads();

#pragma unroll
        for (int i = 0; i < 4; i++) {
            float f = f_sh[ty * 4 + i];
#pragma unroll
            for (int n = 0; n < 8; n++) acc[i][n] *= f;
        }
        {
            const float* src = g_V + (((size_t)(b * T_ + kt * 64 + lr)) * HKV_ + kvh) * D_ + lc;
            float* dv = Vs + lr * 129 + lc;
#pragma unroll
            for (int i = 0; i < 32; i += 4) {
                float4 v = *reinterpret_cast<const float4*>(src + i);
                dv[i] = v.x; dv[i + 1] = v.y; dv[i + 2] = v.z; dv[i + 3] = v.w;
            }
        }
        __syncthreads();

        const float* pb = Ss + (ty * 4) * 65;
        const float* vb = Vs + tx * 8;
#pragma unroll 2
        for (int j = 0; j < 64; j++) {
            float p0 = pb[j];
            float p1 = pb[65 + j];
            float p2 = pb[130 + j];
            float p3 = pb[195 + j];
            const float* vr = vb + j * 129;
#pragma unroll
            for (int n = 0; n < 8; n++) {
                float v = vr[n];
                acc[0][n] += p0 * v;
                acc[1][n] += p1 * v;
                acc[2][n] += p2 * v;
                acc[3][n] += p3 * v;
            }
        }
    }

    __syncthreads();
    float li[4];
#pragma unroll
    for (int i = 0; i < 4; i++) li[i] = 1.0f / l_sh[ty * 4 + i];

    float* dst = g_att + ((size_t)(b * S_ + s0 + ty * 4)) * (HQ_ * D_) + hq * D_ + tx * 8;
#pragma unroll
    for (int i = 0; i < 4; i++) {
        float4 v0 = make_float4(acc[i][0] * li[i], acc[i][1] * li[i],
                                acc[i][2] * li[i], acc[i][3] * li[i]);
        float4 v1 = make_float4(acc[i][4] * li[i], acc[i][5] * li[i],
                                acc[i][6] * li[i], acc[i][7] * li[i]);
        *reinterpret_cast<float4*>(dst + (size_t)i * (HQ_ * D_))     = v0;
        *reinterpret_cast<float4*>(dst + (size_t)i * (HQ_ * D_) + 4) = v1;
    }
}

// ---------------- launcher --------------------------------------------------
extern "C" void kernel_launch(void* const* d_in, const int* in_sizes, int n_in,
                              void* d_out, int out_size)
{
    const float* hidden  = (const float*)d_in[0];
    const float* k_cache = (const float*)d_in[1];
    const float* v_cache = (const float*)d_in[2];
    const float* wq      = (const float*)d_in[3];
    const float* wk      = (const float*)d_in[4];
    const float* wv      = (const float*)d_in[5];
    const float* wo      = (const float*)d_in[6];
    float* out = (float*)d_out;

    float *q, *ktmp, *vtmp, *att;
    cudaGetSymbolAddress((void**)&q,    g_q);
    cudaGetSymbolAddress((void**)&ktmp, g_ktmp);
    cudaGetSymbolAddress((void**)&vtmp, g_vtmp);
    cudaGetSymbolAddress((void**)&att,  g_att);

    __nv_bfloat16 *hid_h, *hid_l, *wq_h, *wq_l, *wk_h, *wk_l, *wv_h, *wv_l,
                  *wo_h, *wo_l, *attb_h, *attb_l;
    cudaGetSymbolAddress((void**)&hid_h,  g_hid_h);
    cudaGetSymbolAddress((void**)&hid_l,  g_hid_l);
    cudaGetSymbolAddress((void**)&wq_h,   g_wqT_h);
    cudaGetSymbolAddress((void**)&wq_l,   g_wqT_l);
    cudaGetSymbolAddress((void**)&wk_h,   g_wkT_h);
    cudaGetSymbolAddress((void**)&wk_l,   g_wkT_l);
    cudaGetSymbolAddress((void**)&wv_h,   g_wvT_h);
    cudaGetSymbolAddress((void**)&wv_l,   g_wvT_l);
    cudaGetSymbolAddress((void**)&wo_h,   g_woT_h);
    cudaGetSymbolAddress((void**)&wo_l,   g_woT_l);
    cudaGetSymbolAddress((void**)&attb_h, g_attb_h);
    cudaGetSymbolAddress((void**)&attb_l, g_attb_l);

    cudaFuncSetAttribute(gemm_bf16,
                         cudaFuncAttributeMaxDynamicSharedMemorySize, GEMM_SMEM);
    cudaFuncSetAttribute(attn_kernel,
                         cudaFuncAttributeMaxDynamicSharedMemorySize, ATT_SMEM_BYTES);

    // ---- conversions (memory bound, ~80us total) ----
    conv_split<<<(NT_ * H_ / 4 + 255) / 256, 256>>>(
        (const float4*)hidden, (uint2*)hid_h, (uint2*)hid_l, NT_ * H_ / 4);
    conv_splitT<<<dim3(H_ / 32, H_ / 32), dim3(32, 8)>>>(wq, wq_h, wq_l, H_, H_);
    conv_splitT<<<dim3((HKV_ * D_) / 32, H_ / 32), dim3(32, 8)>>>(wk, wk_h, wk_l, H_, HKV_ * D_);
    conv_splitT<<<dim3((HKV_ * D_) / 32, H_ / 32), dim3(32, 8)>>>(wv, wv_h, wv_l, H_, HKV_ * D_);
    conv_splitT<<<dim3(H_ / 32, H_ / 32), dim3(32, 8)>>>(wo, wo_h, wo_l, H_, H_);

    // ---- projections (bf16-split tensor GEMM) ----
    gemm_bf16<<<dim3(H_ / 128, NT_ / 128), 256, GEMM_SMEM>>>(
        hid_h, hid_l, wq_h, wq_l, q, NT_, H_, H_);
    gemm_bf16<<<dim3((HKV_ * D_) / 128, NT_ / 128), 256, GEMM_SMEM>>>(
        hid_h, hid_l, wk_h, wk_l, ktmp, NT_, HKV_ * D_, H_);
    gemm_bf16<<<dim3((HKV_ * D_) / 128, NT_ / 128), 256, GEMM_SMEM>>>(
        hid_h, hid_l, wv_h, wv_l, vtmp, NT_, HKV_ * D_, H_);

    // ---- rope + KV assembly ----
    rope_q_kernel<<<(NT_ * HQ_ * 64) / 256, 256>>>();
    rope_scatter_k_kernel<<<(NT_ * HKV_ * 64) / 256, 256>>>();
    scatter_v_kernel<<<(NT_ * HKV_ * D_ / 4) / 256, 256>>>();
    copy_cache_kernel<<<(B_ * L_ * HKV_ * D_ / 4) / 256, 256>>>(
        (const float4*)k_cache, (const float4*)v_cache);

    // ---- attention (fp32 flash) ----
    attn_kernel<<<dim3(S_ / 64, HQ_, B_), 256, ATT_SMEM_BYTES>>>();

    // ---- output projection ----
    conv_split<<<(NT_ * H_ / 4 + 255) / 256, 256>>>(
        (const float4*)att, (uint2*)attb_h, (uint2*)attb_l, NT_ * H_ / 4);
    gemm_bf16<<<dim3(H_ / 128, NT_ / 128), 256, GEMM_SMEM>>>(
        attb_h, attb_l, wo_h, wo_l, out, NT_, H_, H_);
}

// round 5
// speedup vs baseline: 4.7475x; 2.6692x over previous
#include <cuda_runtime.h>
#include <cuda_bf16.h>
#include <math.h>
#include <stdint.h>

// Problem constants
#define B_    8
#define S_    512
#define H_    4096
#define HQ_   32
#define HKV_  8
#define D_    128
#define L_    1536
#define T_    2048
#define NT_   (B_*S_)
#define THETA_ 500000.0f

// ---------------- scratch (device globals) ----------------------------------
__device__ float g_q   [(size_t)NT_*HQ_ *D_];   // Q proj out (fp32)
__device__ float g_ktmp[(size_t)NT_*HKV_*D_];
__device__ float g_vtmp[(size_t)NT_*HKV_*D_];

// bf16 split buffers
__device__ __nv_bfloat16 g_hid_h [(size_t)NT_*H_];
__device__ __nv_bfloat16 g_hid_l [(size_t)NT_*H_];
__device__ __nv_bfloat16 g_wqT_h [(size_t)H_*H_];
__device__ __nv_bfloat16 g_wqT_l [(size_t)H_*H_];
__device__ __nv_bfloat16 g_wkT_h [(size_t)H_*HKV_*D_];
__device__ __nv_bfloat16 g_wkT_l [(size_t)H_*HKV_*D_];
__device__ __nv_bfloat16 g_wvT_h [(size_t)H_*HKV_*D_];
__device__ __nv_bfloat16 g_wvT_l [(size_t)H_*HKV_*D_];
__device__ __nv_bfloat16 g_woT_h [(size_t)H_*H_];
__device__ __nv_bfloat16 g_woT_l [(size_t)H_*H_];
__device__ __nv_bfloat16 g_attb_h[(size_t)NT_*H_];
__device__ __nv_bfloat16 g_attb_l[(size_t)NT_*H_];

// bf16 split Q / K / V for attention
__device__ __nv_bfloat16 g_qb_h[(size_t)NT_*HQ_*D_];
__device__ __nv_bfloat16 g_qb_l[(size_t)NT_*HQ_*D_];
__device__ __nv_bfloat16 g_kb_h[(size_t)B_*T_*HKV_*D_];
__device__ __nv_bfloat16 g_kb_l[(size_t)B_*T_*HKV_*D_];
__device__ __nv_bfloat16 g_vb_h[(size_t)B_*T_*HKV_*D_];
__device__ __nv_bfloat16 g_vb_l[(size_t)B_*T_*HKV_*D_];

// ---------------- helpers ----------------------------------------------------
__device__ __forceinline__ uint32_t smem_u32(const void* p) {
    uint32_t r;
    asm("{ .reg .u64 t; cvta.to.shared.u64 t, %1; cvt.u32.u64 %0, t; }"
        : "=r"(r) : "l"(p));
    return r;
}
__device__ __forceinline__ uint16_t bf_hi(float x) {
    __nv_bfloat16 b = __float2bfloat16(x);
    return *reinterpret_cast<uint16_t*>(&b);
}
__device__ __forceinline__ float bf_back(uint16_t u) {
    __nv_bfloat16 b = *reinterpret_cast<__nv_bfloat16*>(&u);
    return __bfloat162float(b);
}
// pack (lo,hi) floats into bf16x2 register (lo in low half)
__device__ __forceinline__ uint32_t pack_bf2(float lo, float hi) {
    uint32_t r;
    asm("cvt.rn.bf16x2.f32 %0, %1, %2;" : "=r"(r) : "f"(hi), "f"(lo));
    return r;
}
__device__ __forceinline__ float bf2lo(uint32_t p) { return __uint_as_float(p << 16); }
__device__ __forceinline__ float bf2hi(uint32_t p) { return __uint_as_float(p & 0xFFFF0000u); }

#define CP_ASYNC16(dst, src) \
    asm volatile("cp.async.cg.shared.global [%0], [%1], 16;" :: "r"(dst), "l"(src))
#define CP_COMMIT() asm volatile("cp.async.commit_group;")
#define CP_WAIT1()  asm volatile("cp.async.wait_group 1;")
#define CP_WAIT0()  asm volatile("cp.async.wait_group 0;")

#define LDSM4(r, a) \
    asm volatile("ldmatrix.sync.aligned.m8n8.x4.shared.b16 {%0,%1,%2,%3}, [%4];" \
                 : "=r"((r)[0]), "=r"((r)[1]), "=r"((r)[2]), "=r"((r)[3]) : "r"(a))
#define LDSM4T(r, a) \
    asm volatile("ldmatrix.sync.aligned.m8n8.x4.trans.shared.b16 {%0,%1,%2,%3}, [%4];" \
                 : "=r"((r)[0]), "=r"((r)[1]), "=r"((r)[2]), "=r"((r)[3]) : "r"(a))
#define LDSM2(r, a) \
    asm volatile("ldmatrix.sync.aligned.m8n8.x2.shared.b16 {%0,%1}, [%2];" \
                 : "=r"((r)[0]), "=r"((r)[1]) : "r"(a))

#define MMA_BF16(c, a, b0v, b1v) \
    asm volatile("mma.sync.aligned.m16n8k16.row.col.f32.bf16.bf16.f32 " \
                 "{%0,%1,%2,%3}, {%4,%5,%6,%7}, {%8,%9}, {%0,%1,%2,%3};" \
                 : "+f"((c)[0]), "+f"((c)[1]), "+f"((c)[2]), "+f"((c)[3]) \
                 : "r"((a)[0]), "r"((a)[1]), "r"((a)[2]), "r"((a)[3]), \
                   "r"(b0v), "r"(b1v))

// ---------------- fp32 -> bf16 hi/lo split -----------------------------------
__global__ void conv_split(const float4* __restrict__ in,
                           uint2* __restrict__ oh, uint2* __restrict__ ol, int n4)
{
    int i = blockIdx.x * blockDim.x + threadIdx.x;
    if (i >= n4) return;
    float4 v = in[i];
    uint16_t hx = bf_hi(v.x), hy = bf_hi(v.y), hz = bf_hi(v.z), hw = bf_hi(v.w);
    uint16_t lx = bf_hi(v.x - bf_back(hx));
    uint16_t ly = bf_hi(v.y - bf_back(hy));
    uint16_t lz = bf_hi(v.z - bf_back(hz));
    uint16_t lw = bf_hi(v.w - bf_back(hw));
    oh[i] = make_uint2((uint32_t)hx | ((uint32_t)hy << 16),
                       (uint32_t)hz | ((uint32_t)hw << 16));
    ol[i] = make_uint2((uint32_t)lx | ((uint32_t)ly << 16),
                       (uint32_t)lz | ((uint32_t)lw << 16));
}

__global__ void conv_splitT(const float* __restrict__ in,
                            __nv_bfloat16* __restrict__ oh,
                            __nv_bfloat16* __restrict__ ol, int K, int N)
{
    __shared__ float t[32][33];
    const int n0 = blockIdx.x * 32;
    const int k0 = blockIdx.y * 32;
    const int x = threadIdx.x, y = threadIdx.y;
#pragma unroll
    for (int dy = 0; dy < 4; dy++)
        t[y + dy * 8][x] = in[(size_t)(k0 + y + dy * 8) * N + n0 + x];
    __syncthreads();
#pragma unroll
    for (int dy = 0; dy < 4; dy++) {
        int nrow = y + dy * 8;
        float v = t[x][nrow];
        uint16_t h = bf_hi(v);
        uint16_t l = bf_hi(v - bf_back(h));
        size_t o = (size_t)(n0 + nrow) * K + k0 + x;
        oh[o] = *reinterpret_cast<__nv_bfloat16*>(&h);
        ol[o] = *reinterpret_cast<__nv_bfloat16*>(&l);
    }
}

// ============================================================================
// bf16-split GEMM (unchanged from R4). C = A[M,K] @ B[N,K]^T.
// ============================================================================
#define GEMM_SMEM (2 * 32768)

__global__ __launch_bounds__(256) void gemm_bf16(
    const __nv_bfloat16* __restrict__ Ah, const __nv_bfloat16* __restrict__ Al,
    const __nv_bfloat16* __restrict__ Bh, const __nv_bfloat16* __restrict__ Bl,
    float* __restrict__ C, int M, int N, int K)
{
    extern __shared__ char smem[];
    const uint32_t sb = smem_u32(smem);
    const int tid  = threadIdx.x;
    const int lane = tid & 31;
    const int wid  = tid >> 5;
    const int bm   = blockIdx.y * 128;
    const int bn   = blockIdx.x * 128;
    const int wm   = (wid >> 2) * 64;
    const int wn   = (wid & 3) * 32;

    const int lrow = tid >> 2;
    const int lchk = tid & 3;
    const uint32_t dsw = (uint32_t)(lrow * 64 + ((lchk ^ ((lrow >> 1) & 3)) * 16));

    const __nv_bfloat16* srcA[2] = {Ah, Al};
    const __nv_bfloat16* srcB[2] = {Bh, Bl};

    const int arow = ((lane >> 3) & 1) * 8 + (lane & 7);
    const int akc  = lane >> 4;
    const int aph  = ((lane & 7) >> 1) & 3;
    const int brow = lane & 7;
    const int bkc  = (lane >> 3) & 1;
    const int bph  = (brow >> 1) & 3;

    const uint32_t aBase = (uint32_t)((wm + arow) * 64);
    const uint32_t bBase = (uint32_t)((wn + brow) * 64);

    float acc[4][4][4];
#pragma unroll
    for (int i = 0; i < 4; i++)
#pragma unroll
        for (int j = 0; j < 4; j++) {
            acc[i][j][0] = 0.f; acc[i][j][1] = 0.f;
            acc[i][j][2] = 0.f; acc[i][j][3] = 0.f;
        }

    const int nk = K / 32;

    auto issue = [&](int st, int k0) {
        const uint32_t s = sb + st * 32768;
#pragma unroll
        for (int p = 0; p < 2; p++) {
            const __nv_bfloat16* g = srcA[p] + (size_t)(bm + lrow) * K + k0 + lchk * 8;
            uint32_t d = s + p * 8192 + dsw;
            CP_ASYNC16(d, g);
            CP_ASYNC16(d + 4096, g + (size_t)64 * K);
        }
#pragma unroll
        for (int p = 0; p < 2; p++) {
            const __nv_bfloat16* g = srcB[p] + (size_t)(bn + lrow) * K + k0 + lchk * 8;
            uint32_t d = s + 16384 + p * 8192 + dsw;
            CP_ASYNC16(d, g);
            CP_ASYNC16(d + 4096, g + (size_t)64 * K);
        }
        CP_COMMIT();
    };

    issue(0, 0);
    if (nk > 1) issue(1, 32);

    for (int ck = 0; ck < nk; ck++) {
        if (ck + 1 < nk) { CP_WAIT1(); } else { CP_WAIT0(); }
        __syncthreads();

        const uint32_t s  = sb + (ck & 1) * 32768;
        const uint32_t sAh = s + aBase;
        const uint32_t sAl = s + 8192 + aBase;
        const uint32_t sBh = s + 16384 + bBase;
        const uint32_t sBl = s + 24576 + bBase;

#pragma unroll
        for (int ks = 0; ks < 2; ks++) {
            const uint32_t cA = (uint32_t)(((ks * 2 + akc) ^ aph) * 16);
            const uint32_t cB = (uint32_t)(((ks * 2 + bkc) ^ bph) * 16);

            uint32_t aF[4][4];
#pragma unroll
            for (int i = 0; i < 4; i++) LDSM4(aF[i], sAh + i * 1024 + cA);
            uint32_t bH[4][2], bL[4][2];
#pragma unroll
            for (int j = 0; j < 4; j++) LDSM2(bH[j], sBh + j * 512 + cB);
#pragma unroll
            for (int j = 0; j < 4; j++) LDSM2(bL[j], sBl + j * 512 + cB);

#pragma unroll
            for (int i = 0; i < 4; i++)
#pragma unroll
                for (int j = 0; j < 4; j++)
                    MMA_BF16(acc[i][j], aF[i], bH[j][0], bH[j][1]);
#pragma unroll
            for (int i = 0; i < 4; i++)
#pragma unroll
                for (int j = 0; j < 4; j++)
                    MMA_BF16(acc[i][j], aF[i], bL[j][0], bL[j][1]);

#pragma unroll
            for (int i = 0; i < 4; i++) LDSM4(aF[i], sAl + i * 1024 + cA);
#pragma unroll
            for (int i = 0; i < 4; i++)
#pragma unroll
                for (int j = 0; j < 4; j++)
                    MMA_BF16(acc[i][j], aF[i], bH[j][0], bH[j][1]);
        }
        __syncthreads();
        if (ck + 2 < nk) issue(ck & 1, (ck + 2) * 32);
    }

    const int g4 = lane >> 2, t4 = lane & 3;
#pragma unroll
    for (int i = 0; i < 4; i++) {
        const int row = bm + wm + i * 16 + g4;
#pragma unroll
        for (int j = 0; j < 4; j++) {
            const int col = bn + wn + j * 8 + t4 * 2;
            *reinterpret_cast<float2*>(&C[(size_t)row * N + col]) =
                make_float2(acc[i][j][0], acc[i][j][1]);
            *reinterpret_cast<float2*>(&C[(size_t)(row + 8) * N + col]) =
                make_float2(acc[i][j][2], acc[i][j][3]);
        }
    }
}

// ---------------- RoPE Q -> bf16 split ---------------------------------------
__global__ void rope_q_kernel()
{
    int idx = blockIdx.x * blockDim.x + threadIdx.x;
    if (idx >= NT_ * HQ_ * 64) return;
    int d   = idx & 63;
    int th  = idx >> 6;
    int tok = th >> 5;
    int s   = tok & (S_ - 1);
    float pos = (float)(L_ + s);
    float inv = powf(THETA_, -(float)d * (1.0f / 64.0f));
    float ang = pos * inv;
    float c = cosf(ang), sn = sinf(ang);
    const float* base = g_q + (size_t)th * D_;
    float x1 = base[d], x2 = base[d + 64];
    float y1 = x1 * c - x2 * sn;
    float y2 = x2 * c + x1 * sn;
    size_t o = (size_t)th * D_;
    uint16_t h1 = bf_hi(y1), h2 = bf_hi(y2);
    g_qb_h[o + d]      = *reinterpret_cast<__nv_bfloat16*>(&h1);
    g_qb_h[o + d + 64] = *reinterpret_cast<__nv_bfloat16*>(&h2);
    uint16_t l1 = bf_hi(y1 - bf_back(h1)), l2 = bf_hi(y2 - bf_back(h2));
    g_qb_l[o + d]      = *reinterpret_cast<__nv_bfloat16*>(&l1);
    g_qb_l[o + d + 64] = *reinterpret_cast<__nv_bfloat16*>(&l2);
}

// ---------------- RoPE new K -> bf16 split scatter ---------------------------
__global__ void rope_scatter_k_kernel()
{
    int idx = blockIdx.x * blockDim.x + threadIdx.x;
    if (idx >= NT_ * HKV_ * 64) return;
    int d   = idx & 63;
    int th  = idx >> 6;
    int tok = th >> 3;
    int kvh = th & 7;
    int b   = tok >> 9;
    int s   = tok & 511;
    float pos = (float)(L_ + s);
    float inv = powf(THETA_, -(float)d * (1.0f / 64.0f));
    float ang = pos * inv;
    float c = cosf(ang), sn = sinf(ang);
    const float* src = g_ktmp + (size_t)th * D_;
    float x1 = src[d], x2 = src[d + 64];
    float y1 = x1 * c - x2 * sn;
    float y2 = x2 * c + x1 * sn;
    size_t o = (((size_t)(b * T_ + L_ + s)) * HKV_ + kvh) * D_;
    uint16_t h1 = bf_hi(y1), h2 = bf_hi(y2);
    g_kb_h[o + d]      = *reinterpret_cast<__nv_bfloat16*>(&h1);
    g_kb_h[o + d + 64] = *reinterpret_cast<__nv_bfloat16*>(&h2);
    uint16_t l1 = bf_hi(y1 - bf_back(h1)), l2 = bf_hi(y2 - bf_back(h2));
    g_kb_l[o + d]      = *reinterpret_cast<__nv_bfloat16*>(&l1);
    g_kb_l[o + d + 64] = *reinterpret_cast<__nv_bfloat16*>(&l2);
}

// ---------------- new V -> bf16 split scatter --------------------------------
__global__ void scatter_v_kernel()
{
    int idx = blockIdx.x * blockDim.x + threadIdx.x;    // float2 granule
    const int n = NT_ * HKV_ * D_ / 2;
    if (idx >= n) return;
    int e   = idx * 2;
    int tok = e >> 10;                      // / (HKV_*D_)
    int r   = e & 1023;
    int b   = tok >> 9;
    int s   = tok & 511;
    float2 v = reinterpret_cast<const float2*>(g_vtmp)[idx];
    uint16_t hx = bf_hi(v.x), hy = bf_hi(v.y);
    uint16_t lx = bf_hi(v.x - bf_back(hx)), ly = bf_hi(v.y - bf_back(hy));
    size_t o2 = ((((size_t)(b * T_ + L_ + s)) * HKV_) * D_ + r) >> 1;
    reinterpret_cast<uint32_t*>(g_vb_h)[o2] = (uint32_t)hx | ((uint32_t)hy << 16);
    reinterpret_cast<uint32_t*>(g_vb_l)[o2] = (uint32_t)lx | ((uint32_t)ly << 16);
}

// ---------------- cache -> bf16 split ----------------------------------------
__global__ void copy_cache_kernel(const float2* __restrict__ kc,
                                  const float2* __restrict__ vc)
{
    int idx = blockIdx.x * blockDim.x + threadIdx.x;    // float2 granule
    const int n = B_ * L_ * HKV_ * D_ / 2;
    if (idx >= n) return;
    const int perb = L_ * HKV_ * D_ / 2;
    int b = idx / perb;
    size_t o2 = (size_t)idx + (size_t)b * ((T_ - L_) * HKV_ * D_ / 2);
    float2 k = kc[idx];
    float2 v = vc[idx];
    uint16_t khx = bf_hi(k.x), khy = bf_hi(k.y);
    uint16_t klx = bf_hi(k.x - bf_back(khx)), kly = bf_hi(k.y - bf_back(khy));
    uint16_t vhx = bf_hi(v.x), vhy = bf_hi(v.y);
    uint16_t vlx = bf_hi(v.x - bf_back(vhx)), vly = bf_hi(v.y - bf_back(vhy));
    reinterpret_cast<uint32_t*>(g_kb_h)[o2] = (uint32_t)khx | ((uint32_t)khy << 16);
    reinterpret_cast<uint32_t*>(g_kb_l)[o2] = (uint32_t)klx | ((uint32_t)kly << 16);
    reinterpret_cast<uint32_t*>(g_vb_h)[o2] = (uint32_t)vhx | ((uint32_t)vhy << 16);
    reinterpret_cast<uint32_t*>(g_vb_l)[o2] = (uint32_t)vlx | ((uint32_t)vly << 16);
}

// ============================================================================
// Tensor-core flash attention: 128 q-rows x 64 k-cols tiles, bf16 split.
// 8 warps x 16 rows. Q frags in registers; K/V double-buffered via cp.async.
// ============================================================================
#define AT_STAGE 65536                 // Kh 16K | Kl 16K | Vh 16K | Vl 16K
#define AT_SMEM  (2 * AT_STAGE)        // 128KB
#define SC_LOG2E 0.12751884817f        // (1/sqrt(128)) * log2(e)

__global__ __launch_bounds__(256, 1) void attn_mma()
{
    extern __shared__ char smem[];
    const uint32_t sb = smem_u32(smem);
    const int tid  = threadIdx.x;
    const int lane = tid & 31;
    const int w    = tid >> 5;             // 0..7, rows 16w..16w+15
    const int g    = lane >> 2;
    const int t4   = lane & 3;
    const int qt   = blockIdx.x;           // 0..3
    const int hq   = blockIdx.y;
    const int b    = blockIdx.z;
    const int kvh  = hq >> 2;

    // ---- stage Q tile (Qh 32K @0, Ql 32K @32K), then ldmatrix to registers --
    {
        const int qr  = tid >> 1;              // 0..127
        const int qcb = (tid & 1) * 8;
        const size_t qo = ((size_t)(b * S_ + qt * 128 + qr)) * (HQ_ * D_) + hq * D_;
#pragma unroll
        for (int i = 0; i < 8; i++) {
            int ch = qcb + i;
            uint32_t d = sb + qr * 256 + ((ch ^ (qr & 7)) * 16);
            CP_ASYNC16(d,         g_qb_h + qo + ch * 8);
            CP_ASYNC16(d + 32768, g_qb_l + qo + ch * 8);
        }
        CP_COMMIT();
        CP_WAIT0();
    }
    __syncthreads();

    uint32_t qh[8][4], ql[8][4];
    {
        const int tt  = lane >> 3;
        const int qrow = 16 * w + (tt & 1) * 8 + (lane & 7);
        const int chi  = tt >> 1;
#pragma unroll
        for (int kk = 0; kk < 8; kk++) {
            uint32_t a = sb + qrow * 256 + (((2 * kk + chi) ^ (qrow & 7)) * 16);
            LDSM4(qh[kk], a);
            LDSM4(ql[kk], a + 32768);
        }
    }
    __syncthreads();

    // ---- K/V pipeline ----
    const int ntiles = 26 + 2 * qt;
    const int mask_from = 24 + 2 * qt;

    auto issueKV = [&](int stage, int kt) {
        const uint32_t s = sb + stage * AT_STAGE;
        const int trow = tid >> 2;
        const int cb   = (tid & 3) * 4;
        const size_t go = (((size_t)(b * T_ + kt * 64 + trow)) * HKV_ + kvh) * D_;
        const uint32_t rb = s + trow * 256;
#pragma unroll
        for (int i = 0; i < 4; i++) {
            int ch = cb + i;
            uint32_t d = rb + ((ch ^ (trow & 7)) * 16);
            CP_ASYNC16(d,         g_kb_h + go + ch * 8);
            CP_ASYNC16(d + 16384, g_kb_l + go + ch * 8);
            CP_ASYNC16(d + 32768, g_vb_h + go + ch * 8);
            CP_ASYNC16(d + 49152, g_vb_l + go + ch * 8);
        }
        CP_COMMIT();
    };

    issueKV(0, 0);
    issueKV(1, 1);

    float oacc[16][4];
#pragma unroll
    for (int j = 0; j < 16; j++) {
        oacc[j][0] = 0.f; oacc[j][1] = 0.f; oacc[j][2] = 0.f; oacc[j][3] = 0.f;
    }
    float m0 = -1e30f, m1 = -1e30f, l0 = 0.f, l1 = 0.f;

    // precomputed lane addressing
    const int tt   = lane >> 3;
    const int krb  = (tt >> 1) * 8 + (lane & 7);     // K: row-in-pair base
    const int kch1 = tt & 1;                         // K: chunk low bit
    const int vrb  = (tt & 1) * 8 + (lane & 7);      // V: row base
    const int vch1 = tt >> 1;                        // V: chunk low bit

    for (int kt = 0; kt < ntiles; kt++) {
        if (kt + 1 < ntiles) { CP_WAIT1(); } else { CP_WAIT0(); }
        __syncthreads();

        const uint32_t s = sb + (kt & 1) * AT_STAGE;

        // ---- scores: S[16][64] per warp ----
        float sacc[8][4];
#pragma unroll
        for (int j = 0; j < 8; j++) {
            sacc[j][0] = 0.f; sacc[j][1] = 0.f; sacc[j][2] = 0.f; sacc[j][3] = 0.f;
        }
#pragma unroll
        for (int kk = 0; kk < 8; kk++) {
#pragma unroll
            for (int jp = 0; jp < 4; jp++) {
                const int trow = jp * 16 + krb;
                const uint32_t addr = s + trow * 256 +
                                      (((2 * kk + kch1) ^ (trow & 7)) * 16);
                uint32_t bh[4], bl[4];
                LDSM4(bh, addr);
                LDSM4(bl, addr + 16384);
                MMA_BF16(sacc[2*jp],   qh[kk], bh[0], bh[1]);
                MMA_BF16(sacc[2*jp+1], qh[kk], bh[2], bh[3]);
                MMA_BF16(sacc[2*jp],   qh[kk], bl[0], bl[1]);
                MMA_BF16(sacc[2*jp+1], qh[kk], bl[2], bl[3]);
                MMA_BF16(sacc[2*jp],   ql[kk], bh[0], bh[1]);
                MMA_BF16(sacc[2*jp+1], ql[kk], bh[2], bh[3]);
            }
        }

        // ---- mask (diagonal tiles) ----
        if (kt >= mask_from) {
            const int colb = kt * 64 + 2 * t4;
            const int alw0 = L_ + qt * 128 + 16 * w + g;
            const int alw1 = alw0 + 8;
#pragma unroll
            for (int j = 0; j < 8; j++) {
                int c0 = colb + j * 8;
                if (c0 > alw0)     sacc[j][0] = -1e30f;
                if (c0 + 1 > alw0) sacc[j][1] = -1e30f;
                if (c0 > alw1)     sacc[j][2] = -1e30f;
                if (c0 + 1 > alw1) sacc[j][3] = -1e30f;
            }
        }

        // ---- online softmax ----
        float rm0 = -1e30f, rm1 = -1e30f;
#pragma unroll
        for (int j = 0; j < 8; j++) {
            rm0 = fmaxf(rm0, fmaxf(sacc[j][0], sacc[j][1]));
            rm1 = fmaxf(rm1, fmaxf(sacc[j][2], sacc[j][3]));
        }
        rm0 = fmaxf(rm0, __shfl_xor_sync(0xFFFFFFFFu, rm0, 1));
        rm0 = fmaxf(rm0, __shfl_xor_sync(0xFFFFFFFFu, rm0, 2));
        rm1 = fmaxf(rm1, __shfl_xor_sync(0xFFFFFFFFu, rm1, 1));
        rm1 = fmaxf(rm1, __shfl_xor_sync(0xFFFFFFFFu, rm1, 2));

        const float nm0 = fmaxf(m0, rm0), nm1 = fmaxf(m1, rm1);
        const float f0 = exp2f((m0 - nm0) * SC_LOG2E);
        const float f1 = exp2f((m1 - nm1) * SC_LOG2E);
        float rs0 = 0.f, rs1 = 0.f;
#pragma unroll
        for (int j = 0; j < 8; j++) {
            sacc[j][0] = exp2f((sacc[j][0] - nm0) * SC_LOG2E);
            sacc[j][1] = exp2f((sacc[j][1] - nm0) * SC_LOG2E);
            sacc[j][2] = exp2f((sacc[j][2] - nm1) * SC_LOG2E);
            sacc[j][3] = exp2f((sacc[j][3] - nm1) * SC_LOG2E);
            rs0 += sacc[j][0] + sacc[j][1];
            rs1 += sacc[j][2] + sacc[j][3];
        }
        rs0 += __shfl_xor_sync(0xFFFFFFFFu, rs0, 1);
        rs0 += __shfl_xor_sync(0xFFFFFFFFu, rs0, 2);
        rs1 += __shfl_xor_sync(0xFFFFFFFFu, rs1, 1);
        rs1 += __shfl_xor_sync(0xFFFFFFFFu, rs1, 2);
        l0 = l0 * f0 + rs0;
        l1 = l1 * f1 + rs1;
        m0 = nm0; m1 = nm1;

#pragma unroll
        for (int j = 0; j < 16; j++) {
            oacc[j][0] *= f0; oacc[j][1] *= f0;
            oacc[j][2] *= f1; oacc[j][3] *= f1;
        }

        // ---- P fragments (hi + lo) from score accumulators ----
        uint32_t ph[4][4], pl[4][4];
#pragma unroll
        for (int kc = 0; kc < 4; kc++) {
            float v00 = sacc[2*kc][0],   v01 = sacc[2*kc][1];
            float v02 = sacc[2*kc][2],   v03 = sacc[2*kc][3];
            float v10 = sacc[2*kc+1][0], v11 = sacc[2*kc+1][1];
            float v12 = sacc[2*kc+1][2], v13 = sacc[2*kc+1][3];
            ph[kc][0] = pack_bf2(v00, v01);
            ph[kc][1] = pack_bf2(v02, v03);
            ph[kc][2] = pack_bf2(v10, v11);
            ph[kc][3] = pack_bf2(v12, v13);
            pl[kc][0] = pack_bf2(v00 - bf2lo(ph[kc][0]), v01 - bf2hi(ph[kc][0]));
            pl[kc][1] = pack_bf2(v02 - bf2lo(ph[kc][1]), v03 - bf2hi(ph[kc][1]));
            pl[kc][2] = pack_bf2(v10 - bf2lo(ph[kc][2]), v11 - bf2hi(ph[kc][2]));
            pl[kc][3] = pack_bf2(v12 - bf2lo(ph[kc][3]), v13 - bf2hi(ph[kc][3]));
        }

        // ---- O += P @ V ----
        const uint32_t vbase = s + 32768;
#pragma unroll
        for (int jp2 = 0; jp2 < 8; jp2++) {
#pragma unroll
            for (int kc = 0; kc < 4; kc++) {
                const int trow = kc * 16 + vrb;
                const uint32_t addr = vbase + trow * 256 +
                                      (((jp2 * 2 + vch1) ^ (trow & 7)) * 16);
                uint32_t vh[4], vl[4];
                LDSM4T(vh, addr);
                LDSM4T(vl, addr + 16384);
                MMA_BF16(oacc[2*jp2],   ph[kc], vh[0], vh[1]);
                MMA_BF16(oacc[2*jp2+1], ph[kc], vh[2], vh[3]);
                MMA_BF16(oacc[2*jp2],   ph[kc], vl[0], vl[1]);
                MMA_BF16(oacc[2*jp2+1], ph[kc], vl[2], vl[3]);
                MMA_BF16(oacc[2*jp2],   pl[kc], vh[0], vh[1]);
                MMA_BF16(oacc[2*jp2+1], pl[kc], vh[2], vh[3]);
            }
        }

        __syncthreads();
        if (kt + 2 < ntiles) issueKV(kt & 1, kt + 2);
    }

    // ---- epilogue: O /= l, write bf16 hi/lo split ----
    const float il0 = 1.0f / l0;
    const float il1 = 1.0f / l1;
    const size_t tok0 = (size_t)(b * S_ + qt * 128 + 16 * w + g);
    uint32_t* oh32 = reinterpret_cast<uint32_t*>(g_attb_h);
    uint32_t* ol32 = reinterpret_cast<uint32_t*>(g_attb_l);
#pragma unroll
    for (int jn = 0; jn < 16; jn++) {
        float o0 = oacc[jn][0] * il0, o1 = oacc[jn][1] * il0;
        float o2 = oacc[jn][2] * il1, o3 = oacc[jn][3] * il1;
        const size_t a0 = (tok0 * (HQ_ * D_) + hq * D_ + jn * 8 + 2 * t4) >> 1;
        const size_t a1 = a0 + (8 * (HQ_ * D_) >> 1);
        uint32_t h01 = pack_bf2(o0, o1);
        uint32_t h23 = pack_bf2(o2, o3);
        oh32[a0] = h01;
        oh32[a1] = h23;
        ol32[a0] = pack_bf2(o0 - bf2lo(h01), o1 - bf2hi(h01));
        ol32[a1] = pack_bf2(o2 - bf2lo(h23), o3 - bf2hi(h23));
    }
}

// ---------------- launcher ---------------------------------------------------
extern "C" void kernel_launch(void* const* d_in, const int* in_sizes, int n_in,
                              void* d_out, int out_size)
{
    const float* hidden  = (const float*)d_in[0];
    const float* k_cache = (const float*)d_in[1];
    const float* v_cache = (const float*)d_in[2];
    const float* wq      = (const float*)d_in[3];
    const float* wk      = (const float*)d_in[4];
    const float* wv      = (const float*)d_in[5];
    const float* wo      = (const float*)d_in[6];
    float* out = (float*)d_out;

    float *q, *ktmp, *vtmp;
    cudaGetSymbolAddress((void**)&q,    g_q);
    cudaGetSymbolAddress((void**)&ktmp, g_ktmp);
    cudaGetSymbolAddress((void**)&vtmp, g_vtmp);

    __nv_bfloat16 *hid_h, *hid_l, *wq_h, *wq_l, *wk_h, *wk_l, *wv_h, *wv_l,
                  *wo_h, *wo_l, *attb_h, *attb_l;
    cudaGetSymbolAddress((void**)&hid_h,  g_hid_h);
    cudaGetSymbolAddress((void**)&hid_l,  g_hid_l);
    cudaGetSymbolAddress((void**)&wq_h,   g_wqT_h);
    cudaGetSymbolAddress((void**)&wq_l,   g_wqT_l);
    cudaGetSymbolAddress((void**)&wk_h,   g_wkT_h);
    cudaGetSymbolAddress((void**)&wk_l,   g_wkT_l);
    cudaGetSymbolAddress((void**)&wv_h,   g_wvT_h);
    cudaGetSymbolAddress((void**)&wv_l,   g_wvT_l);
    cudaGetSymbolAddress((void**)&wo_h,   g_woT_h);
    cudaGetSymbolAddress((void**)&wo_l,   g_woT_l);
    cudaGetSymbolAddress((void**)&attb_h, g_attb_h);
    cudaGetSymbolAddress((void**)&attb_l, g_attb_l);

    cudaFuncSetAttribute(gemm_bf16,
                         cudaFuncAttributeMaxDynamicSharedMemorySize, GEMM_SMEM);
    cudaFuncSetAttribute(attn_mma,
                         cudaFuncAttributeMaxDynamicSharedMemorySize, AT_SMEM);

    // conversions
    conv_split<<<(NT_ * H_ / 4 + 255) / 256, 256>>>(
        (const float4*)hidden, (uint2*)hid_h, (uint2*)hid_l, NT_ * H_ / 4);
    conv_splitT<<<dim3(H_ / 32, H_ / 32), dim3(32, 8)>>>(wq, wq_h, wq_l, H_, H_);
    conv_splitT<<<dim3((HKV_ * D_) / 32, H_ / 32), dim3(32, 8)>>>(wk, wk_h, wk_l, H_, HKV_ * D_);
    conv_splitT<<<dim3((HKV_ * D_) / 32, H_ / 32), dim3(32, 8)>>>(wv, wv_h, wv_l, H_, HKV_ * D_);
    conv_splitT<<<dim3(H_ / 32, H_ / 32), dim3(32, 8)>>>(wo, wo_h, wo_l, H_, H_);

    // projections
    gemm_bf16<<<dim3(H_ / 128, NT_ / 128), 256, GEMM_SMEM>>>(
        hid_h, hid_l, wq_h, wq_l, q, NT_, H_, H_);
    gemm_bf16<<<dim3((HKV_ * D_) / 128, NT_ / 128), 256, GEMM_SMEM>>>(
        hid_h, hid_l, wk_h, wk_l, ktmp, NT_, HKV_ * D_, H_);
    gemm_bf16<<<dim3((HKV_ * D_) / 128, NT_ / 128), 256, GEMM_SMEM>>>(
        hid_h, hid_l, wv_h, wv_l, vtmp, NT_, HKV_ * D_, H_);

    // rope + KV assembly (bf16 split)
    rope_q_kernel<<<(NT_ * HQ_ * 64) / 256, 256>>>();
    rope_scatter_k_kernel<<<(NT_ * HKV_ * 64) / 256, 256>>>();
    scatter_v_kernel<<<(NT_ * HKV_ * D_ / 2) / 256, 256>>>();
    copy_cache_kernel<<<(B_ * L_ * HKV_ * D_ / 2) / 256, 256>>>(
        (const float2*)k_cache, (const float2*)v_cache);

    // attention (tensor-core flash)
    attn_mma<<<dim3(S_ / 128, HQ_, B_), 256, AT_SMEM>>>();

    // output projection
    gemm_bf16<<<dim3(H_ / 128, NT_ / 128), 256, GEMM_SMEM>>>(
        attb_h, attb_l, wo_h, wo_l, out, NT_, H_, H_);
}